// round 1
// baseline (speedup 1.0000x reference)
#include <cuda_runtime.h>
#include <math.h>

#define BS 128
#define T  32
#define DH 128
#define NS 512
#define EPSF 1e-8f

// ---------------- scratch (static device globals; no runtime alloc) ----------------
__device__ float g_mem[BS*NS*DH];     // memory matrix (33.5 MB, L2-resident)
__device__ float g_xW [T*BS*DH];      // precomputed x@Wxh + bh, layout [t][b][i]
__device__ float g_h  [BS*DH];
__device__ float g_r  [BS*DH];
__device__ float g_wprev[BS*NS];
__device__ float g_kr [BS*DH];
__device__ float g_kw [BS*DH];
__device__ float g_e  [BS*DH];
__device__ float g_a  [BS*DH];
__device__ float g_scal[BS*12];       // beta_r,g_r,s_r0..2,gam_r, beta_w,g_w,s_w0..2,gam_w
__device__ float g_hall[T*BS*DH];     // h per step for deferred output GEMM
__device__ float g_rall[T*BS*DH];

// ---------------- helpers ----------------
__device__ __forceinline__ float softplusf(float x) {
    return fmaxf(x, 0.f) + log1pf(expf(-fabsf(x)));
}
__device__ __forceinline__ float sigmoidf(float x) {
    return 1.f / (1.f + expf(-x));
}

// block reductions for 512 threads (16 warps)
__device__ __forceinline__ float blk_sum512(float v, float* red) {
    #pragma unroll
    for (int o = 16; o; o >>= 1) v += __shfl_xor_sync(0xffffffffu, v, o);
    int w = threadIdx.x >> 5, l = threadIdx.x & 31;
    __syncthreads();
    if (l == 0) red[w] = v;
    __syncthreads();
    if (threadIdx.x < 16) {
        v = red[threadIdx.x];
        #pragma unroll
        for (int o = 8; o; o >>= 1) v += __shfl_xor_sync(0x0000ffffu, v, o);
        if (threadIdx.x == 0) red[0] = v;
    }
    __syncthreads();
    return red[0];
}
__device__ __forceinline__ float blk_max512(float v, float* red) {
    #pragma unroll
    for (int o = 16; o; o >>= 1) v = fmaxf(v, __shfl_xor_sync(0xffffffffu, v, o));
    int w = threadIdx.x >> 5, l = threadIdx.x & 31;
    __syncthreads();
    if (l == 0) red[w] = v;
    __syncthreads();
    if (threadIdx.x < 16) {
        v = red[threadIdx.x];
        #pragma unroll
        for (int o = 8; o; o >>= 1) v = fmaxf(v, __shfl_xor_sync(0x0000ffffu, v, o));
        if (threadIdx.x == 0) red[0] = v;
    }
    __syncthreads();
    return red[0];
}

// ---------------- init ----------------
__global__ void init_kernel() {
    int i = blockIdx.x * blockDim.x + threadIdx.x;
    int stride = gridDim.x * blockDim.x;
    for (int k = i; k < BS*NS*DH; k += stride) g_mem[k] = 1e-6f;
    for (int k = i; k < BS*NS;    k += stride) g_wprev[k] = 1.0f / (float)NS;
    for (int k = i; k < BS*DH;    k += stride) { g_h[k] = 0.f; g_r[k] = 0.f; }
}

// ---------------- precompute x @ Wxh + bh ----------------
// grid 128 blocks x 128 threads; each block: 32 rows of (b*32+t)
__global__ void xw_kernel(const float* __restrict__ x,
                          const float* __restrict__ Wxh,
                          const float* __restrict__ bh) {
    __shared__ float xs[32][DH];
    int r0  = blockIdx.x * 32;
    int tid = threadIdx.x;
    for (int idx = tid; idx < 32*DH; idx += 128)
        xs[idx >> 7][idx & 127] = x[(r0 + (idx >> 7)) * DH + (idx & 127)];
    __syncthreads();
    int j = tid;
    float acc[32];
    #pragma unroll
    for (int rr = 0; rr < 32; rr++) acc[rr] = 0.f;
    for (int i = 0; i < DH; i++) {
        float w = Wxh[i * DH + j];
        #pragma unroll
        for (int rr = 0; rr < 32; rr++) acc[rr] += xs[rr][i] * w;
    }
    float bb = bh[j];
    #pragma unroll
    for (int rr = 0; rr < 32; rr++) {
        int row = r0 + rr;             // row = b*32 + t
        int b = row >> 5, t = row & 31;
        g_xW[(t * BS + b) * DH + j] = acc[rr] + bb;
    }
}

// ---------------- per-step: h, o, activations ----------------
// grid 16 blocks x 256 threads; block handles 8 batches
__global__ void ho_kernel(int t,
                          const float* __restrict__ Whh, const float* __restrict__ Wrh,
                          const float* __restrict__ Wr,  const float* __restrict__ br,
                          const float* __restrict__ Ww,  const float* __restrict__ bw) {
    __shared__ float hs[8][DH], rs[8][DH], hn[8][DH];
    __shared__ float osm[8][524];
    int b0  = blockIdx.x * 8;
    int tid = threadIdx.x;

    for (int idx = tid; idx < 8*DH; idx += 256) {
        int bl = idx >> 7, i = idx & 127;
        hs[bl][i] = g_h[(b0 + bl) * DH + i];
        rs[bl][i] = g_r[(b0 + bl) * DH + i];
    }
    __syncthreads();

    // h = tanh(xW + h@Whh + r@Wrh)
    {
        int i = tid & 127, bp = tid >> 7;   // bp in {0,1}
        float a0 = g_xW[(t*BS + b0 + bp    ) * DH + i];
        float a1 = g_xW[(t*BS + b0 + bp + 2) * DH + i];
        float a2 = g_xW[(t*BS + b0 + bp + 4) * DH + i];
        float a3 = g_xW[(t*BS + b0 + bp + 6) * DH + i];
        #pragma unroll 4
        for (int jj = 0; jj < DH; jj++) {
            float w1 = Whh[jj * DH + i];
            float w2 = Wrh[jj * DH + i];
            a0 += hs[bp    ][jj] * w1 + rs[bp    ][jj] * w2;
            a1 += hs[bp + 2][jj] * w1 + rs[bp + 2][jj] * w2;
            a2 += hs[bp + 4][jj] * w1 + rs[bp + 4][jj] * w2;
            a3 += hs[bp + 6][jj] * w1 + rs[bp + 6][jj] * w2;
        }
        float h0 = tanhf(a0), h1 = tanhf(a1), h2 = tanhf(a2), h3 = tanhf(a3);
        hn[bp    ][i] = h0;  hn[bp + 2][i] = h1;
        hn[bp + 4][i] = h2;  hn[bp + 6][i] = h3;
        g_h[(b0+bp  )*DH+i] = h0; g_h[(b0+bp+2)*DH+i] = h1;
        g_h[(b0+bp+4)*DH+i] = h2; g_h[(b0+bp+6)*DH+i] = h3;
        g_hall[(t*BS+b0+bp  )*DH+i] = h0; g_hall[(t*BS+b0+bp+2)*DH+i] = h1;
        g_hall[(t*BS+b0+bp+4)*DH+i] = h2; g_hall[(t*BS+b0+bp+6)*DH+i] = h3;
    }
    __syncthreads();

    // o_r = h@Wr + br (134 cols), o_w = h@Ww + bw (390 cols); combined c in [0,524)
    for (int c = tid; c < 524; c += 256) {
        const float* W; int ld, cc; float bias;
        if (c < 134) { W = Wr; ld = 134; cc = c;       bias = br[cc]; }
        else         { W = Ww; ld = 390; cc = c - 134; bias = bw[cc]; }
        float acc[8];
        #pragma unroll
        for (int bl = 0; bl < 8; bl++) acc[bl] = bias;
        #pragma unroll 4
        for (int jj = 0; jj < DH; jj++) {
            float w = W[jj * ld + cc];
            #pragma unroll
            for (int bl = 0; bl < 8; bl++) acc[bl] += hn[bl][jj] * w;
        }
        #pragma unroll
        for (int bl = 0; bl < 8; bl++) osm[bl][c] = acc[bl];
    }
    __syncthreads();

    // activations
    for (int idx = tid; idx < 8*524; idx += 256) {
        int bl = idx / 524, c = idx % 524;
        int b = b0 + bl;
        float v = osm[bl][c];
        if (c < DH) {
            g_kr[b*DH + c] = v;
        } else if (c < 134) {
            int cc = c - DH;
            if (cc == 0) g_scal[b*12 + 0] = softplusf(v);
            else if (cc == 1) g_scal[b*12 + 1] = sigmoidf(v);
            else if (cc == 2) {
                float v0 = osm[bl][130], v1 = osm[bl][131], v2 = osm[bl][132];
                float m = fmaxf(v0, fmaxf(v1, v2));
                float e0 = expf(v0-m), e1 = expf(v1-m), e2 = expf(v2-m);
                float s = e0 + e1 + e2;
                g_scal[b*12 + 2] = e0/s; g_scal[b*12 + 3] = e1/s; g_scal[b*12 + 4] = e2/s;
            }
            else if (cc == 5) g_scal[b*12 + 5] = 1.0f + softplusf(v);
        } else {
            int cw = c - 134;
            if (cw < DH) {
                g_kw[b*DH + cw] = v;
            } else if (cw < 134) {
                int cc = cw - DH;
                if (cc == 0) g_scal[b*12 + 6] = softplusf(v);
                else if (cc == 1) g_scal[b*12 + 7] = sigmoidf(v);
                else if (cc == 2) {
                    float v0 = osm[bl][264], v1 = osm[bl][265], v2 = osm[bl][266];
                    float m = fmaxf(v0, fmaxf(v1, v2));
                    float e0 = expf(v0-m), e1 = expf(v1-m), e2 = expf(v2-m);
                    float s = e0 + e1 + e2;
                    g_scal[b*12 + 8] = e0/s; g_scal[b*12 + 9] = e1/s; g_scal[b*12 + 10] = e2/s;
                }
                else if (cc == 5) g_scal[b*12 + 11] = 1.0f + softplusf(v);
            } else if (cw < 262) {
                g_e[b*DH + (cw - 134)] = sigmoidf(v);
            } else {
                g_a[b*DH + (cw - 262)] = tanhf(v);
            }
        }
    }
}

// ---------------- per-step: attention (read+write), readout, mem update ----------------
// grid BS blocks x 512 threads; one block per batch. mem read 2x, written 1x.
__global__ void attn_kernel(int t) {
    __shared__ float s_dr[NS], s_dw[NS], s_nrm[NS];
    __shared__ float s_wg[NS], s_wr[NS], s_ww[NS];
    __shared__ float s_kr[DH], s_kw[DH];
    __shared__ float s_red[16];
    __shared__ float s_kn[2];

    int b    = blockIdx.x;
    int tid  = threadIdx.x;
    int lane = tid & 31, wid = tid >> 5;   // 16 warps

    if (tid < DH) { s_kr[tid] = g_kr[b*DH + tid]; s_kw[tid] = g_kw[b*DH + tid]; }
    __syncthreads();

    // k norms (warp 0)
    if (wid == 0) {
        float sr = 0.f, sw = 0.f;
        #pragma unroll
        for (int j = lane; j < DH; j += 32) {
            float a = s_kr[j], c = s_kw[j];
            sr += a*a; sw += c*c;
        }
        #pragma unroll
        for (int o = 16; o; o >>= 1) {
            sr += __shfl_xor_sync(0xffffffffu, sr, o);
            sw += __shfl_xor_sync(0xffffffffu, sw, o);
        }
        if (lane == 0) { s_kn[0] = sqrtf(sr); s_kn[1] = sqrtf(sw); }
    }

    // phase 1: dots + row norms. warp per row, lane holds one float4 of the row.
    float4 kr4 = reinterpret_cast<float4*>(s_kr)[lane];
    float4 kw4 = reinterpret_cast<float4*>(s_kw)[lane];
    for (int n = wid; n < NS; n += 16) {
        const float4* row = reinterpret_cast<const float4*>(g_mem + (b*NS + n) * DH);
        float4 v = row[lane];
        float dr = v.x*kr4.x + v.y*kr4.y + v.z*kr4.z + v.w*kr4.w;
        float dw = v.x*kw4.x + v.y*kw4.y + v.z*kw4.z + v.w*kw4.w;
        float ss = v.x*v.x   + v.y*v.y   + v.z*v.z   + v.w*v.w;
        #pragma unroll
        for (int o = 16; o; o >>= 1) {
            dr += __shfl_xor_sync(0xffffffffu, dr, o);
            dw += __shfl_xor_sync(0xffffffffu, dw, o);
            ss += __shfl_xor_sync(0xffffffffu, ss, o);
        }
        if (lane == 0) { s_dr[n] = dr; s_dw[n] = dw; s_nrm[n] = sqrtf(ss); }
    }
    __syncthreads();

    float beta_r = g_scal[b*12+0], gr = g_scal[b*12+1];
    float s0r = g_scal[b*12+2], s1r = g_scal[b*12+3], s2r = g_scal[b*12+4];
    float gam_r = g_scal[b*12+5];
    float beta_w = g_scal[b*12+6], gw = g_scal[b*12+7];
    float s0w = g_scal[b*12+8], s1w = g_scal[b*12+9], s2w = g_scal[b*12+10];
    float gam_w = g_scal[b*12+11];
    float knr = s_kn[0], knw = s_kn[1];

    int n = tid;

    // read attention (w_prev from global carry)
    float wprev = g_wprev[b*NS + n];
    {
        float c  = beta_r * s_dr[n] / (s_nrm[n] * knr + EPSF);
        float m  = blk_max512(c, s_red);
        float ex = expf(c - m);
        float se = blk_sum512(ex, s_red);
        float wc = ex / se;
        float wg = gr * wc + (1.f - gr) * wprev;
        s_wg[n] = wg;
        __syncthreads();
        float wt = s0r * s_wg[(n+1) & (NS-1)] + s1r * wg + s2r * s_wg[(n-1) & (NS-1)];
        float w  = powf(wt, gam_r);
        float sw_ = blk_sum512(w, s_red);
        s_wr[n] = w / (sw_ + EPSF);
    }
    __syncthreads();

    // write attention (w_prev = w_r)
    {
        float c  = beta_w * s_dw[n] / (s_nrm[n] * knw + EPSF);
        float m  = blk_max512(c, s_red);
        float ex = expf(c - m);
        float se = blk_sum512(ex, s_red);
        float wc = ex / se;
        float wg = gw * wc + (1.f - gw) * s_wr[n];
        __syncthreads();           // all reads of s_wg from read phase are done (blk_sum synced)
        s_wg[n] = wg;
        __syncthreads();
        float wt = s0w * s_wg[(n+1) & (NS-1)] + s1w * wg + s2w * s_wg[(n-1) & (NS-1)];
        float w  = powf(wt, gam_w);
        float sw_ = blk_sum512(w, s_red);
        float ww = w / (sw_ + EPSF);
        s_ww[n] = ww;
        g_wprev[b*NS + n] = ww;    // carry for next step
    }
    __syncthreads();

    // phase 4: r = w_r . mem (old), then mem update, single pass
    {
        int j = tid & 127, chunk = tid >> 7;      // 4 chunks of 128 slots
        float e_j = g_e[b*DH + j], a_j = g_a[b*DH + j];
        float racc = 0.f;
        int nbase = chunk * 128;
        #pragma unroll 4
        for (int q = 0; q < 128; q++) {
            int nn = nbase + q;
            int idx = (b*NS + nn) * DH + j;
            float v = g_mem[idx];
            racc += s_wr[nn] * v;
            float wwn = s_ww[nn];
            g_mem[idx] = v * (1.f - wwn * e_j) + wwn * a_j;
        }
        s_dr[tid] = racc;                          // reuse scratch
        __syncthreads();
        if (tid < DH) {
            float r = s_dr[tid] + s_dr[128 + tid] + s_dr[256 + tid] + s_dr[384 + tid];
            g_r[b*DH + tid] = r;
            g_rall[(t*BS + b)*DH + tid] = r;
        }
    }
}

// ---------------- deferred output GEMM: y = [h, r] @ Wout + bout ----------------
// grid 128 blocks x 128 threads; each block: 32 rows of (t*BS+b)
__global__ void y_kernel(const float* __restrict__ Wout,
                         const float* __restrict__ bout,
                         float* __restrict__ out) {
    __shared__ float sh[32][DH], sr[32][DH];
    int r0  = blockIdx.x * 32;
    int tid = threadIdx.x;
    for (int idx = tid; idx < 32*DH; idx += 128) {
        int rr = idx >> 7, i = idx & 127;
        sh[rr][i] = g_hall[(r0 + rr)*DH + i];
        sr[rr][i] = g_rall[(r0 + rr)*DH + i];
    }
    __syncthreads();
    int j = tid;
    float acc[32];
    #pragma unroll
    for (int rr = 0; rr < 32; rr++) acc[rr] = 0.f;
    for (int i = 0; i < DH; i++) {
        float w1 = Wout[i * DH + j];
        float w2 = Wout[(DH + i) * DH + j];
        #pragma unroll
        for (int rr = 0; rr < 32; rr++) acc[rr] += sh[rr][i] * w1 + sr[rr][i] * w2;
    }
    float bb = bout[j];
    #pragma unroll
    for (int rr = 0; rr < 32; rr++) {
        int row = r0 + rr;                 // row = t*BS + b
        int tt = row >> 7, b = row & 127;
        out[(b * T + tt) * DH + j] = acc[rr] + bb;
    }
}

// ---------------- launch ----------------
extern "C" void kernel_launch(void* const* d_in, const int* in_sizes, int n_in,
                              void* d_out, int out_size) {
    const float* x    = (const float*)d_in[0];
    const float* Wxh  = (const float*)d_in[1];
    const float* Whh  = (const float*)d_in[2];
    const float* Wrh  = (const float*)d_in[3];
    const float* bh   = (const float*)d_in[4];
    const float* Wout = (const float*)d_in[5];
    const float* bout = (const float*)d_in[6];
    const float* Wr   = (const float*)d_in[7];
    const float* br   = (const float*)d_in[8];
    const float* Ww   = (const float*)d_in[9];
    const float* bw   = (const float*)d_in[10];
    float* out = (float*)d_out;

    init_kernel<<<1024, 256>>>();
    xw_kernel<<<(BS*T)/32, 128>>>(x, Wxh, bh);
    for (int t = 0; t < T; t++) {
        ho_kernel<<<BS/8, 256>>>(t, Whh, Wrh, Wr, br, Ww, bw);
        attn_kernel<<<BS, 512>>>(t);
    }
    y_kernel<<<(BS*T)/32, 128>>>(Wout, bout, out);
}

// round 2
// speedup vs baseline: 2.5949x; 2.5949x over previous
#include <cuda_runtime.h>
#include <math.h>

#define BS 128
#define T  32
#define DH 128
#define NS 512
#define EPSF 1e-8f
#define NT 1024

// ---------------- scratch ----------------
__device__ float g_mem[BS*NS*DH];     // 33.5 MB
__device__ float g_xW [T*BS*DH];      // x@Wxh + bh, [t][b][i]
__device__ float g_h  [BS*DH];
__device__ float g_r  [BS*DH];
__device__ float g_wprev[BS*NS];
__device__ float g_hall[T*BS*DH];
__device__ float g_rall[T*BS*DH];

// ---------------- helpers ----------------
__device__ __forceinline__ float softplusf(float x) {
    return fmaxf(x, 0.f) + log1pf(expf(-fabsf(x)));
}
__device__ __forceinline__ float sigmoidf(float x) {
    return 1.f / (1.f + __expf(-x));
}

// 1024-thread block reductions (32 warps)
__device__ __forceinline__ float redsum(float v, float* r32) {
    #pragma unroll
    for (int o = 16; o; o >>= 1) v += __shfl_xor_sync(0xffffffffu, v, o);
    int w = threadIdx.x >> 5;
    __syncthreads();
    if ((threadIdx.x & 31) == 0) r32[w] = v;
    __syncthreads();
    if (threadIdx.x < 32) {
        v = r32[threadIdx.x];
        #pragma unroll
        for (int o = 16; o; o >>= 1) v += __shfl_xor_sync(0xffffffffu, v, o);
        if (threadIdx.x == 0) r32[0] = v;
    }
    __syncthreads();
    return r32[0];
}
__device__ __forceinline__ float redmax(float v, float* r32) {
    #pragma unroll
    for (int o = 16; o; o >>= 1) v = fmaxf(v, __shfl_xor_sync(0xffffffffu, v, o));
    int w = threadIdx.x >> 5;
    __syncthreads();
    if ((threadIdx.x & 31) == 0) r32[w] = v;
    __syncthreads();
    if (threadIdx.x < 32) {
        v = r32[threadIdx.x];
        #pragma unroll
        for (int o = 16; o; o >>= 1) v = fmaxf(v, __shfl_xor_sync(0xffffffffu, v, o));
        if (threadIdx.x == 0) r32[0] = v;
    }
    __syncthreads();
    return r32[0];
}

// ---------------- init ----------------
__global__ void init_kernel() {
    int i = blockIdx.x * blockDim.x + threadIdx.x;
    int stride = gridDim.x * blockDim.x;
    for (int k = i; k < BS*NS*DH; k += stride) g_mem[k] = 1e-6f;
    for (int k = i; k < BS*NS;    k += stride) g_wprev[k] = 1.0f / (float)NS;
    for (int k = i; k < BS*DH;    k += stride) { g_h[k] = 0.f; g_r[k] = 0.f; }
}

// ---------------- x @ Wxh + bh ----------------
__global__ void xw_kernel(const float* __restrict__ x,
                          const float* __restrict__ Wxh,
                          const float* __restrict__ bh) {
    __shared__ float xs[32][DH];
    int r0  = blockIdx.x * 32;
    int tid = threadIdx.x;
    for (int idx = tid; idx < 32*DH; idx += 128)
        xs[idx >> 7][idx & 127] = x[(r0 + (idx >> 7)) * DH + (idx & 127)];
    __syncthreads();
    int j = tid;
    float acc[32];
    #pragma unroll
    for (int rr = 0; rr < 32; rr++) acc[rr] = 0.f;
    for (int i = 0; i < DH; i++) {
        float w = Wxh[i * DH + j];
        #pragma unroll
        for (int rr = 0; rr < 32; rr++) acc[rr] += xs[rr][i] * w;
    }
    float bb = bh[j];
    #pragma unroll
    for (int rr = 0; rr < 32; rr++) {
        int row = r0 + rr;             // row = b*32 + t
        int b = row >> 5, t = row & 31;
        g_xW[(t * BS + b) * DH + j] = acc[rr] + bb;
    }
}

// ---------------- fused step: GEMMs + activations + attention + update ----------------
// grid BS blocks x 1024 threads; one block per batch.
__global__ __launch_bounds__(NT, 1)
void step_kernel(int t,
                 const float* __restrict__ Whh, const float* __restrict__ Wrh,
                 const float* __restrict__ Wr,  const float* __restrict__ br,
                 const float* __restrict__ Ww,  const float* __restrict__ bw) {
    __shared__ float sh_h[DH], sh_r[DH], sh_hn[DH];
    __shared__ float osm[524];
    __shared__ float sh_kr[DH], sh_kw[DH];
    __shared__ float s_dr[NS], s_dw[NS], s_nrm[NS];
    __shared__ float s_wg[NS], s_wr[NS], s_ww[NS];
    __shared__ float red[4096];          // GEMM partials / phase-F float4 partials
    __shared__ float r32[32];
    __shared__ float s_kn[2];
    __shared__ float s_par[12];

    int b    = blockIdx.x;
    int tid  = threadIdx.x;
    int lane = tid & 31, wid = tid >> 5;   // 32 warps

    if (tid < DH) { sh_h[tid] = g_h[b*DH + tid]; sh_r[tid] = g_r[b*DH + tid]; }
    __syncthreads();

    // --- h = tanh(xW + h@Whh + r@Wrh): 8-way split over jj ---
    {
        int j = tid & 127, sl = tid >> 7;
        float acc = 0.f;
        int j0 = sl * 16;
        #pragma unroll
        for (int q = 0; q < 16; q++) {
            int jj = j0 + q;
            acc += sh_h[jj] * Whh[jj*DH + j] + sh_r[jj] * Wrh[jj*DH + j];
        }
        red[sl*DH + j] = acc;
    }
    __syncthreads();
    if (tid < DH) {
        float a = g_xW[(t*BS + b)*DH + tid];
        #pragma unroll
        for (int sl = 0; sl < 8; sl++) a += red[sl*DH + tid];
        float h = tanhf(a);
        sh_hn[tid] = h;
        g_h[b*DH + tid] = h;
        g_hall[(t*BS + b)*DH + tid] = h;
    }
    __syncthreads();

    // --- o = h@[Wr|Ww] + bias: cols 0..511 split 2-way over jj, tail 512..523 ---
    {
        int col = tid & 511, half = tid >> 9;
        const float* W; int ld, cc;
        if (col < 134) { W = Wr; ld = 134; cc = col; }
        else           { W = Ww; ld = 390; cc = col - 134; }
        float acc = 0.f;
        int j0 = half * 64;
        #pragma unroll 8
        for (int q = 0; q < 64; q++) {
            int jj = j0 + q;
            acc += sh_hn[jj] * W[jj*ld + cc];
        }
        red[tid] = acc;
    }
    if (tid < 12) {                        // combined cols 512..523 -> Ww cols 378..389
        int cc = 378 + tid;
        float acc = bw[cc];
        #pragma unroll 8
        for (int jj = 0; jj < DH; jj++) acc += sh_hn[jj] * Ww[jj*390 + cc];
        osm[512 + tid] = acc;
    }
    __syncthreads();
    if (tid < 512) {
        float v = red[tid] + red[tid + 512];
        v += (tid < 134) ? br[tid] : bw[tid - 134];
        osm[tid] = v;
    }
    __syncthreads();

    // --- activations (in smem, no global round-trip) ---
    if (tid < 128)       sh_kr[tid]       = osm[tid];
    else if (tid < 256)  sh_kw[tid - 128] = osm[tid + 6];      // osm[134..261]
    else if (tid < 384)  osm[tid + 12]    = sigmoidf(osm[tid + 12]);   // e: osm[268..395]
    else if (tid < 512)  osm[tid + 12]    = tanhf(osm[tid + 12]);      // a: osm[396..523]
    else if (tid == 512) {
        s_par[0] = softplusf(osm[128]);
        s_par[1] = sigmoidf(osm[129]);
        {
            float v0 = osm[130], v1 = osm[131], v2 = osm[132];
            float m = fmaxf(v0, fmaxf(v1, v2));
            float e0 = __expf(v0-m), e1 = __expf(v1-m), e2 = __expf(v2-m);
            float s = e0 + e1 + e2;
            s_par[2] = e0/s; s_par[3] = e1/s; s_par[4] = e2/s;
        }
        s_par[5] = 1.0f + softplusf(osm[133]);
        s_par[6] = softplusf(osm[262]);
        s_par[7] = sigmoidf(osm[263]);
        {
            float v0 = osm[264], v1 = osm[265], v2 = osm[266];
            float m = fmaxf(v0, fmaxf(v1, v2));
            float e0 = __expf(v0-m), e1 = __expf(v1-m), e2 = __expf(v2-m);
            float s = e0 + e1 + e2;
            s_par[8] = e0/s; s_par[9] = e1/s; s_par[10] = e2/s;
        }
        s_par[11] = 1.0f + softplusf(osm[267]);
    }
    __syncthreads();

    // --- key norms (warps 0,1) ---
    if (wid < 2) {
        const float* k = wid ? sh_kw : sh_kr;
        float s = 0.f;
        #pragma unroll
        for (int j = lane; j < DH; j += 32) { float a = k[j]; s += a*a; }
        #pragma unroll
        for (int o = 16; o; o >>= 1) s += __shfl_xor_sync(0xffffffffu, s, o);
        if (lane == 0) s_kn[wid] = sqrtf(s);
    }

    // --- phase 1: dots + row norms; warp per row, 2 rows in flight ---
    {
        float4 kr4 = reinterpret_cast<float4*>(sh_kr)[lane];
        float4 kw4 = reinterpret_cast<float4*>(sh_kw)[lane];
        const float4* memb = reinterpret_cast<const float4*>(g_mem + (size_t)b*NS*DH);
        for (int n0 = wid; n0 < NS; n0 += 64) {
            int n1 = n0 + 32;
            float4 v0 = memb[n0*32 + lane];
            float4 v1 = memb[n1*32 + lane];
            float dr0 = v0.x*kr4.x + v0.y*kr4.y + v0.z*kr4.z + v0.w*kr4.w;
            float dw0 = v0.x*kw4.x + v0.y*kw4.y + v0.z*kw4.z + v0.w*kw4.w;
            float ss0 = v0.x*v0.x + v0.y*v0.y + v0.z*v0.z + v0.w*v0.w;
            float dr1 = v1.x*kr4.x + v1.y*kr4.y + v1.z*kr4.z + v1.w*kr4.w;
            float dw1 = v1.x*kw4.x + v1.y*kw4.y + v1.z*kw4.z + v1.w*kw4.w;
            float ss1 = v1.x*v1.x + v1.y*v1.y + v1.z*v1.z + v1.w*v1.w;
            #pragma unroll
            for (int o = 16; o; o >>= 1) {
                dr0 += __shfl_xor_sync(0xffffffffu, dr0, o);
                dw0 += __shfl_xor_sync(0xffffffffu, dw0, o);
                ss0 += __shfl_xor_sync(0xffffffffu, ss0, o);
                dr1 += __shfl_xor_sync(0xffffffffu, dr1, o);
                dw1 += __shfl_xor_sync(0xffffffffu, dw1, o);
                ss1 += __shfl_xor_sync(0xffffffffu, ss1, o);
            }
            if (lane == 0) {
                s_dr[n0] = dr0; s_dw[n0] = dw0; s_nrm[n0] = sqrtf(ss0);
                s_dr[n1] = dr1; s_dw[n1] = dw1; s_nrm[n1] = sqrtf(ss1);
            }
        }
    }
    __syncthreads();

    int n = tid;
    bool act = (tid < NS);

    // --- read attention ---
    {
        float wprev = act ? g_wprev[b*NS + n] : 0.f;
        float c  = act ? s_par[0] * s_dr[n] / (s_nrm[n] * s_kn[0] + EPSF) : -INFINITY;
        float m  = redmax(c, r32);
        float ex = act ? __expf(c - m) : 0.f;
        float se = redsum(ex, r32);
        if (act) {
            float gr = s_par[1];
            s_wg[n] = gr * (ex / se) + (1.f - gr) * wprev;
        }
        __syncthreads();
        float w = 0.f;
        if (act) {
            float wt = s_par[2] * s_wg[(n+1) & (NS-1)] + s_par[3] * s_wg[n]
                     + s_par[4] * s_wg[(n-1) & (NS-1)];
            w = __powf(wt, s_par[5]);
        }
        float sw_ = redsum(w, r32);
        if (act) s_wr[n] = w / (sw_ + EPSF);
    }
    __syncthreads();

    // --- write attention (w_prev = w_r) ---
    {
        float c  = act ? s_par[6] * s_dw[n] / (s_nrm[n] * s_kn[1] + EPSF) : -INFINITY;
        float m  = redmax(c, r32);
        float ex = act ? __expf(c - m) : 0.f;
        float se = redsum(ex, r32);
        if (act) {
            float gw = s_par[7];
            s_wg[n] = gw * (ex / se) + (1.f - gw) * s_wr[n];
        }
        __syncthreads();
        float w = 0.f;
        if (act) {
            float wt = s_par[8] * s_wg[(n+1) & (NS-1)] + s_par[9] * s_wg[n]
                     + s_par[10] * s_wg[(n-1) & (NS-1)];
            w = __powf(wt, s_par[11]);
        }
        float sw_ = redsum(w, r32);
        if (act) {
            float ww = w / (sw_ + EPSF);
            s_ww[n] = ww;
            g_wprev[b*NS + n] = ww;
        }
    }
    __syncthreads();

    // --- phase F: r = w_r . mem (old) + mem update, float4, warp streams full rows ---
    {
        int j4 = tid & 31, ch = tid >> 5;      // 32 chunks of 16 rows; warp covers one full row
        const float4* e4p = reinterpret_cast<const float4*>(osm + 268);
        const float4* a4p = reinterpret_cast<const float4*>(osm + 396);
        float4 e4 = e4p[j4], a4 = a4p[j4];
        float4 racc = make_float4(0.f, 0.f, 0.f, 0.f);
        float4* memb = reinterpret_cast<float4*>(g_mem + (size_t)b*NS*DH);
        int nb = ch * 16;
        #pragma unroll 8
        for (int q = 0; q < 16; q++) {
            int nn = nb + q;
            float4 v = memb[nn*32 + j4];
            float wrn = s_wr[nn], wwn = s_ww[nn];
            racc.x += wrn * v.x; racc.y += wrn * v.y;
            racc.z += wrn * v.z; racc.w += wrn * v.w;
            float4 o;
            o.x = v.x * (1.f - wwn * e4.x) + wwn * a4.x;
            o.y = v.y * (1.f - wwn * e4.y) + wwn * a4.y;
            o.z = v.z * (1.f - wwn * e4.z) + wwn * a4.z;
            o.w = v.w * (1.f - wwn * e4.w) + wwn * a4.w;
            memb[nn*32 + j4] = o;
        }
        reinterpret_cast<float4*>(red)[ch*32 + j4] = racc;
    }
    __syncthreads();
    if (tid < DH) {
        int j4 = tid >> 2, comp = tid & 3;
        float r = 0.f;
        #pragma unroll
        for (int ch = 0; ch < 32; ch++) r += red[(ch*32 + j4)*4 + comp];
        g_r[b*DH + tid] = r;
        g_rall[(t*BS + b)*DH + tid] = r;
    }
}

// ---------------- deferred output GEMM ----------------
__global__ void y_kernel(const float* __restrict__ Wout,
                         const float* __restrict__ bout,
                         float* __restrict__ out) {
    __shared__ float sh[32][DH], sr[32][DH];
    int r0  = blockIdx.x * 32;
    int tid = threadIdx.x;
    for (int idx = tid; idx < 32*DH; idx += 128) {
        int rr = idx >> 7, i = idx & 127;
        sh[rr][i] = g_hall[(r0 + rr)*DH + i];
        sr[rr][i] = g_rall[(r0 + rr)*DH + i];
    }
    __syncthreads();
    int j = tid;
    float acc[32];
    #pragma unroll
    for (int rr = 0; rr < 32; rr++) acc[rr] = 0.f;
    for (int i = 0; i < DH; i++) {
        float w1 = Wout[i * DH + j];
        float w2 = Wout[(DH + i) * DH + j];
        #pragma unroll
        for (int rr = 0; rr < 32; rr++) acc[rr] += sh[rr][i] * w1 + sr[rr][i] * w2;
    }
    float bb = bout[j];
    #pragma unroll
    for (int rr = 0; rr < 32; rr++) {
        int row = r0 + rr;                 // row = t*BS + b
        int tt = row >> 7, bb2 = row & 127;
        out[(bb2 * T + tt) * DH + j] = acc[rr] + bb;
    }
}

// ---------------- launch ----------------
extern "C" void kernel_launch(void* const* d_in, const int* in_sizes, int n_in,
                              void* d_out, int out_size) {
    const float* x    = (const float*)d_in[0];
    const float* Wxh  = (const float*)d_in[1];
    const float* Whh  = (const float*)d_in[2];
    const float* Wrh  = (const float*)d_in[3];
    const float* bh   = (const float*)d_in[4];
    const float* Wout = (const float*)d_in[5];
    const float* bout = (const float*)d_in[6];
    const float* Wr   = (const float*)d_in[7];
    const float* br   = (const float*)d_in[8];
    const float* Ww   = (const float*)d_in[9];
    const float* bw   = (const float*)d_in[10];
    float* out = (float*)d_out;

    init_kernel<<<1024, 256>>>();
    xw_kernel<<<(BS*T)/32, 128>>>(x, Wxh, bh);
    for (int t = 0; t < T; t++) {
        step_kernel<<<BS, NT>>>(t, Whh, Wrh, Wr, br, Ww, bw);
    }
    y_kernel<<<(BS*T)/32, 128>>>(Wout, bout, out);
}